// round 3
// baseline (speedup 1.0000x reference)
#include <cuda_runtime.h>
#include <math.h>

// ---------------------------------------------------------------------------
// ToolCallingModule fused pipeline, fp32 (decision boundaries require fp32).
// Scratch lives in __device__ globals (no allocation allowed in kernel_launch).
// ---------------------------------------------------------------------------

#define NTOK_MAX 16384

__device__ int   g_count;
__device__ int   g_active_tok[NTOK_MAX];
__device__ int   g_active_tool[NTOK_MAX];
__device__ float g_h1[NTOK_MAX * 512];          //  32 MB
__device__ float g_logits[NTOK_MAX * 128];      //   8 MB
__device__ float g_p1[NTOK_MAX * 512];          //  32 MB
__device__ float g_tr[NTOK_MAX * 2048];         // 128 MB
__device__ float g_r1[NTOK_MAX * 512];          //  32 MB

__global__ void reset_kernel() { g_count = 0; }

// ---------------------------------------------------------------------------
// Tiled SGEMM: C[M,N] = act(A[M,K] @ W[K,N] + bias)
// BM=BN=128, BK=8, 256 threads, 8x8 per thread, double-buffered smem.
// AMODE 0: dense A rows (row index = m)
// AMODE 1: A row m = concat(hidden[g_active_tok[m]] (2048), emb[g_active_tool[m]] (256))
// AMODE 2: A row m = concat(hidden[g_active_tok[m]] (2048), A1[m] (2048))
// DYNM:    effective M = g_count (guarded tail)
// SCATTER: C row index = g_active_tok[m]
// ---------------------------------------------------------------------------
template<int AMODE, bool DYNM, bool RELU, bool SCATTER>
__global__ void __launch_bounds__(256, 2)
gemm_kernel(const float* __restrict__ A0, const float* __restrict__ A1,
            const float* __restrict__ W, const float* __restrict__ bias,
            float* __restrict__ C, int M, int K, int N)
{
    __shared__ float As[2][8][128];
    __shared__ float Ws[2][8][128];

    const int m_count = DYNM ? g_count : M;
    const int mb = blockIdx.y * 128;
    if (mb >= m_count) return;
    const int nb = blockIdx.x * 128;

    const int tid  = threadIdx.x;
    const int arow = tid >> 1;           // 0..127
    const int akc  = (tid & 1) << 2;     // 0 or 4
    const int wkr  = tid >> 5;           // 0..7
    const int wnc  = (tid & 31) << 2;    // 0..124

    const int  gr = mb + arow;
    const bool rv = (!DYNM) || (gr < m_count);

    const float* pa0;
    const float* pa1 = nullptr;
    if (AMODE == 0) {
        pa0 = A0 + (size_t)(rv ? gr : 0) * (size_t)K;
    } else {
        const int tok = rv ? g_active_tok[gr] : 0;
        pa0 = A0 + (size_t)tok * 2048;
        if (AMODE == 1) {
            const int tool = rv ? g_active_tool[gr] : 0;
            pa1 = A1 + (size_t)tool * 256;
        } else {
            pa1 = A1 + (size_t)(rv ? gr : 0) * 2048;
        }
    }
    const float* pw = W + (size_t)wkr * N + nb + wnc;

    const int tx = tid & 15;
    const int ty = tid >> 4;

    float acc[8][8];
#pragma unroll
    for (int i = 0; i < 8; i++)
#pragma unroll
        for (int j = 0; j < 8; j++) acc[i][j] = 0.f;

    const int nkt = K >> 3;
    float4 a_reg, w_reg;

    // prefetch k-tile 0 (gk = akc < 2048 always, so pa0 side only)
    if (!rv) a_reg = make_float4(0.f, 0.f, 0.f, 0.f);
    else     a_reg = *(const float4*)(pa0 + akc);
    w_reg = *(const float4*)(pw);

    As[0][akc + 0][arow] = a_reg.x;
    As[0][akc + 1][arow] = a_reg.y;
    As[0][akc + 2][arow] = a_reg.z;
    As[0][akc + 3][arow] = a_reg.w;
    *(float4*)&Ws[0][wkr][wnc] = w_reg;
    __syncthreads();

    int buf = 0;
    for (int kt = 0; kt < nkt; kt++) {
        const bool more = (kt + 1 < nkt);
        if (more) {
            const int gk = (kt + 1) * 8 + akc;
            if (AMODE == 0) {
                a_reg = rv ? *(const float4*)(pa0 + gk) : make_float4(0.f, 0.f, 0.f, 0.f);
            } else {
                if (!rv)            a_reg = make_float4(0.f, 0.f, 0.f, 0.f);
                else if (gk < 2048) a_reg = *(const float4*)(pa0 + gk);
                else                a_reg = *(const float4*)(pa1 + (gk - 2048));
            }
            w_reg = *(const float4*)(pw + (size_t)(kt + 1) * 8 * N);
        }
#pragma unroll
        for (int k = 0; k < 8; k++) {
            float4 a0  = *(const float4*)&As[buf][k][ty * 4];
            float4 a1v = *(const float4*)&As[buf][k][64 + ty * 4];
            float4 b0  = *(const float4*)&Ws[buf][k][tx * 4];
            float4 b1v = *(const float4*)&Ws[buf][k][64 + tx * 4];
            float av[8] = {a0.x, a0.y, a0.z, a0.w, a1v.x, a1v.y, a1v.z, a1v.w};
            float bv[8] = {b0.x, b0.y, b0.z, b0.w, b1v.x, b1v.y, b1v.z, b1v.w};
#pragma unroll
            for (int i = 0; i < 8; i++)
#pragma unroll
                for (int j = 0; j < 8; j++)
                    acc[i][j] += av[i] * bv[j];
        }
        if (more) {
            buf ^= 1;
            As[buf][akc + 0][arow] = a_reg.x;
            As[buf][akc + 1][arow] = a_reg.y;
            As[buf][akc + 2][arow] = a_reg.z;
            As[buf][akc + 3][arow] = a_reg.w;
            *(float4*)&Ws[buf][wkr][wnc] = w_reg;
            __syncthreads();
        }
    }

    // epilogue: bias + optional relu, store (optionally scattered by token)
    float4 bs0 = *(const float4*)(bias + nb + tx * 4);
    float4 bs1 = *(const float4*)(bias + nb + 64 + tx * 4);
    float bcol[8] = {bs0.x, bs0.y, bs0.z, bs0.w, bs1.x, bs1.y, bs1.z, bs1.w};

#pragma unroll
    for (int i = 0; i < 8; i++) {
        const int rl = (i < 4) ? (ty * 4 + i) : (64 + ty * 4 + (i - 4));
        const int r  = mb + rl;
        if (DYNM && r >= m_count) continue;
        const int crow = SCATTER ? g_active_tok[r] : r;
        float* cp = C + (size_t)crow * N + nb;
        float v[8];
#pragma unroll
        for (int j = 0; j < 8; j++) {
            float x = acc[i][j] + bcol[j];
            v[j] = RELU ? fmaxf(x, 0.f) : x;
        }
        *(float4*)(cp + tx * 4)      = make_float4(v[0], v[1], v[2], v[3]);
        *(float4*)(cp + 64 + tx * 4) = make_float4(v[4], v[5], v[6], v[7]);
    }
}

// ---------------------------------------------------------------------------
// Per-token: gate dot, softmax(write probs), top-3 (tie -> lower index),
// valid/last_k logic, active-token compaction, passthrough copy for inactive.
// One block (128 threads = 4 warps) per token; warp-shuffle reductions.
// ---------------------------------------------------------------------------
__device__ __forceinline__ float warp_sum(float v) {
#pragma unroll
    for (int s = 16; s > 0; s >>= 1) v += __shfl_xor_sync(0xffffffffu, v, s);
    return v;
}
__device__ __forceinline__ float warp_max(float v) {
#pragma unroll
    for (int s = 16; s > 0; s >>= 1) v = fmaxf(v, __shfl_xor_sync(0xffffffffu, v, s));
    return v;
}
__device__ __forceinline__ unsigned long long warp_maxull(unsigned long long v) {
#pragma unroll
    for (int s = 16; s > 0; s >>= 1) {
        unsigned long long o = __shfl_xor_sync(0xffffffffu, v, s);
        v = (o > v) ? o : v;
    }
    return v;
}

__global__ void select_kernel(const float* __restrict__ hidden,
                              const float* __restrict__ gate_w,
                              const float* __restrict__ gate_b,
                              float* __restrict__ out_enh,
                              float* __restrict__ out_probs,
                              float* __restrict__ out_call)
{
    const int t    = blockIdx.x;
    const int tid  = threadIdx.x;    // 0..127
    const int lane = tid & 31;
    const int wrp  = tid >> 5;       // 0..3

    __shared__ float sredf[4];
    __shared__ unsigned long long sredu[4];
    __shared__ float s_gate;
    __shared__ int   s_top[3];
    __shared__ int   s_active;

    const float* hrow = hidden + (size_t)t * 2048;

    // ---- gate logit = h . gate_w + gate_b  (should_call = logit > 0) ----
    float acc = 0.f;
#pragma unroll
    for (int i = 0; i < 16; i++)
        acc += hrow[tid + i * 128] * gate_w[tid + i * 128];
    acc = warp_sum(acc);
    if (lane == 0) sredf[wrp] = acc;
    __syncthreads();
    if (tid == 0) s_gate = sredf[0] + sredf[1] + sredf[2] + sredf[3] + gate_b[0];
    __syncthreads();
    const bool should = s_gate > 0.f;

    // ---- softmax over 128 logits (thread tid owns tool tid) ----
    const float lg = g_logits[(size_t)t * 128 + tid];
    float m = warp_max(lg);
    if (lane == 0) sredf[wrp] = m;
    __syncthreads();
    const float mx = fmaxf(fmaxf(sredf[0], sredf[1]), fmaxf(sredf[2], sredf[3]));
    const float e = expf(lg - mx);
    float sm = warp_sum(e);
    __syncthreads();
    if (lane == 0) sredf[wrp] = sm;
    __syncthreads();
    const float denom = sredf[0] + sredf[1] + sredf[2] + sredf[3];
    out_probs[(size_t)t * 128 + tid] = e / denom;

    // ---- top-3 by logit; ties -> lower index (matches jax.lax.top_k) ----
    // key = (orderable float bits << 32) | (127 - tid): max-reduce picks
    // highest logit, lowest index on ties.
    unsigned fb = __float_as_uint(lg);
    fb = (fb & 0x80000000u) ? ~fb : (fb | 0x80000000u);  // monotone float->uint
    unsigned long long key =
        ((unsigned long long)fb << 32) | (unsigned)(127 - tid);

    for (int kk = 0; kk < 3; kk++) {
        unsigned long long k2 = warp_maxull(key);
        if (lane == 0) sredu[wrp] = k2;
        __syncthreads();
        if (tid == 0) {
            unsigned long long best = sredu[0];
            if (sredu[1] > best) best = sredu[1];
            if (sredu[2] > best) best = sredu[2];
            if (sredu[3] > best) best = sredu[3];
            s_top[kk] = 127 - (int)(best & 0xffffffffu);
        }
        __syncthreads();
        if (tid == s_top[kk]) key = 0;  // remove winner
    }

    if (tid == 0) {
        int last = -1, selt = 0;
#pragma unroll
        for (int kk = 0; kk < 3; kk++) {
            if (should && s_top[kk] < 64) { last = kk; selt = s_top[kk]; }
        }
        out_call[t] = should ? 1.f : 0.f;
        if (last >= 0) {
            const int pos = atomicAdd(&g_count, 1);
            g_active_tok[pos]  = t;
            g_active_tool[pos] = selt;
            s_active = 1;
        } else {
            s_active = 0;
        }
    }
    __syncthreads();

    if (!s_active) {
        // enhanced = hidden passthrough
        const float4* hv = (const float4*)hrow;
        float4* ov = (float4*)(out_enh + (size_t)t * 2048);
#pragma unroll
        for (int i = 0; i < 4; i++)
            ov[tid + i * 128] = hv[tid + i * 128];
    }
}

// ---------------------------------------------------------------------------
extern "C" void kernel_launch(void* const* d_in, const int* in_sizes, int n_in,
                              void* d_out, int out_size)
{
    if (n_in < 16) return;
    const float* hidden = (const float*)d_in[0];
    const float* emb    = (const float*)d_in[1];
    const float* gate_w = (const float*)d_in[2];
    const float* gate_b = (const float*)d_in[3];
    const float* sel_w1 = (const float*)d_in[4];
    const float* sel_b1 = (const float*)d_in[5];
    const float* sel_w2 = (const float*)d_in[6];
    const float* sel_b2 = (const float*)d_in[7];
    const float* pg_w1  = (const float*)d_in[8];
    const float* pg_b1  = (const float*)d_in[9];
    const float* pg_w2  = (const float*)d_in[10];
    const float* pg_b2  = (const float*)d_in[11];
    const float* ri_w1  = (const float*)d_in[12];
    const float* ri_b1  = (const float*)d_in[13];
    const float* ri_w2  = (const float*)d_in[14];
    const float* ri_b2  = (const float*)d_in[15];

    const int Ntok = in_sizes[0] / 2048;   // 16384
    float* out       = (float*)d_out;
    float* out_enh   = out;
    float* out_probs = out + (size_t)Ntok * 2048;
    float* out_call  = out_probs + (size_t)Ntok * 128;

    float *p_h1, *p_logits, *p_p1, *p_tr, *p_r1;
    cudaGetSymbolAddress((void**)&p_h1,     g_h1);
    cudaGetSymbolAddress((void**)&p_logits, g_logits);
    cudaGetSymbolAddress((void**)&p_p1,     g_p1);
    cudaGetSymbolAddress((void**)&p_tr,     g_tr);
    cudaGetSymbolAddress((void**)&p_r1,     g_r1);

    const int MB = (Ntok + 127) / 128;     // 128

    reset_kernel<<<1, 1>>>();

    // selector MLP (all tokens): h1 = relu(h @ sel_w1 + b1); logits = h1 @ sel_w2 + b2
    gemm_kernel<0, false, true,  false><<<dim3(4,  MB), 256>>>(hidden, nullptr, sel_w1, sel_b1, p_h1,     Ntok, 2048, 512);
    gemm_kernel<0, false, false, false><<<dim3(1,  MB), 256>>>(p_h1,   nullptr, sel_w2, sel_b2, p_logits, Ntok, 512,  128);

    // gate + softmax + top3 + compaction + passthrough
    select_kernel<<<Ntok, 128>>>(hidden, gate_w, gate_b, out_enh, out_probs, out_call);

    // param generator MLP (active tokens only, selected tool only)
    gemm_kernel<1, true,  true,  false><<<dim3(4,  MB), 256>>>(hidden, emb,  pg_w1, pg_b1, p_p1, Ntok, 2304, 512);
    gemm_kernel<0, true,  false, false><<<dim3(16, MB), 256>>>(p_p1, nullptr, pg_w2, pg_b2, p_tr, Ntok, 512,  2048);

    // result integration MLP (active tokens), scatter into enhanced output
    gemm_kernel<2, true,  true,  false><<<dim3(4,  MB), 256>>>(hidden, p_tr, ri_w1, ri_b1, p_r1,    Ntok, 4096, 512);
    gemm_kernel<0, true,  false, true ><<<dim3(16, MB), 256>>>(p_r1, nullptr, ri_w2, ri_b2, out_enh, Ntok, 512,  2048);
}